// round 4
// baseline (speedup 1.0000x reference)
#include <cuda_runtime.h>
#include <cstdint>
#include <cstddef>

namespace {

constexpr int THREADS   = 448;   // 14 warps
constexpr int BPB       = 16;    // batches per block
constexpr int ROWS      = 224;   // BPB * 14
constexpr int XS_STRIDE = 36;    // 36 % 32 == 4 -> A-frag conflict-free
constexpr int WS_STRIDE = 136;   // 136 % 32 == 8 -> B-frag conflict-free
constexpr int HS_STRIDE = 132;   // 132 % 32 == 4 -> A-frag conflict-free
constexpr int W2S_STRIDE = 72;   // 72 % 32 == 8 -> B-frag conflict-free
constexpr int ZS_STRIDE = 72;

constexpr int XBUF      = ROWS * XS_STRIDE;     // 8064 floats per buffer
constexpr int WBUF      = 32 * WS_STRIDE;       // 4352 floats per buffer
constexpr int WS_OFF    = 2 * XBUF;             // 16128
constexpr int HS_FLOATS = ROWS * HS_STRIDE;     // 29568 (aliases X/W buffers)
constexpr int W2S_OFF   = HS_FLOATS;            // 29568
constexpr int SMEM_FLOATS = W2S_OFF + 128 * W2S_STRIDE;  // 38784
constexpr int SMEM_BYTES  = SMEM_FLOATS * 4;             // 155136

__device__ __forceinline__ float to_tf32(float x) {
    unsigned u;
    asm("cvt.rna.tf32.f32 %0, %1;" : "=r"(u) : "f"(x));
    return __uint_as_float(u);
}

__device__ __forceinline__ void mma8(float* d,
                                     float a0, float a1, float a2, float a3,
                                     float b0, float b1) {
    asm volatile(
        "mma.sync.aligned.m16n8k8.row.col.f32.tf32.tf32.f32 "
        "{%0,%1,%2,%3}, {%4,%5,%6,%7}, {%8,%9}, {%0,%1,%2,%3};\n"
        : "+f"(d[0]), "+f"(d[1]), "+f"(d[2]), "+f"(d[3])
        : "r"(__float_as_uint(a0)), "r"(__float_as_uint(a1)),
          "r"(__float_as_uint(a2)), "r"(__float_as_uint(a3)),
          "r"(__float_as_uint(b0)), "r"(__float_as_uint(b1)));
}

// Hardcoded A_hat = D^{-1/2}(A+I)D^{-1/2} for the fixed 14-tooth graph.
// Degrees (with self-loop): [3,4,4,4,4,4,3, 3,4,4,4,4,4,3].
__device__ __forceinline__ void ahat14(const float* y, float* o) {
    const float A = 0.3333333333333333f;   // 1/sqrt(3*3)
    const float B = 0.28867513459481287f;  // 1/sqrt(3*4)
    const float C = 0.25f;                 // 1/sqrt(4*4)
    o[0]  = A*y[0] + B*y[1] + A*y[7];
    o[1]  = B*y[0] + C*y[1] + C*y[2]  + C*y[8];
    o[2]  = C*y[1] + C*y[2] + C*y[3]  + C*y[9];
    o[3]  = C*y[2] + C*y[3] + C*y[4]  + C*y[10];
    o[4]  = C*y[3] + C*y[4] + C*y[5]  + C*y[11];
    o[5]  = C*y[4] + C*y[5] + B*y[6]  + C*y[12];
    o[6]  = B*y[5] + A*y[6] + A*y[13];
    o[7]  = A*y[0] + A*y[7] + B*y[8];
    o[8]  = C*y[1] + B*y[7] + C*y[8]  + C*y[9];
    o[9]  = C*y[2] + C*y[8] + C*y[9]  + C*y[10];
    o[10] = C*y[3] + C*y[9] + C*y[10] + C*y[11];
    o[11] = C*y[4] + C*y[10]+ C*y[11] + C*y[12];
    o[12] = C*y[5] + C*y[11]+ C*y[12] + B*y[13];
    o[13] = A*y[6] + B*y[12]+ A*y[13];
}

} // namespace

__global__ void __launch_bounds__(THREADS, 1)
gcn_fused_kernel(const float* __restrict__ fea,
                 const float* __restrict__ W1,
                 const float* __restrict__ b1,
                 const float* __restrict__ W2,
                 const float* __restrict__ b2,
                 float* __restrict__ out)
{
    extern __shared__ float sm[];
    float* Xs  = sm;              // [2][ROWS][36]  (GEMM1 X double buffer)
    float* Ws  = sm + WS_OFF;     // [2][32][136]   (GEMM1 W1 double buffer)
    float* Hs  = sm;              // [ROWS][132]    aliases X/W buffers
    float* W2s = sm + W2S_OFF;    // [128][72]
    float* Zs  = sm;              // [ROWS][72]     aliases Hs (after GEMM2)

    const int tid  = threadIdx.x;
    const int warp = tid >> 5;
    const int lane = tid & 31;
    const int g = lane >> 2;   // groupID
    const int t = lane & 3;    // threadID_in_group
    const int wm = warp >> 1;  // 0..6  (M tile, 32 rows)
    const int wn = warp & 1;   // 0..1  (N tile)
    const int blk = blockIdx.x;

    // ---------------- stage W2 -> smem (tf32) ----------------
    #pragma unroll
    for (int j = 0; j < 5; ++j) {
        int idx = tid + j * THREADS;
        if (idx < 2048) {                  // 128*64/4 float4s
            int kr = idx >> 4;
            int q  = (idx & 15) << 2;
            float4 v = *reinterpret_cast<const float4*>(W2 + kr * 64 + q);
            *reinterpret_cast<float4*>(W2s + kr * W2S_STRIDE + q) =
                make_float4(to_tf32(v.x), to_tf32(v.y), to_tf32(v.z), to_tf32(v.w));
        }
    }

    const float* feaB = fea + (size_t)blk * ROWS * 256;

    float4 xr[4];   // X prefetch: 1792 float4 / 448 threads = 4 each
    float4 wr[3];   // W prefetch: 1024 float4 -> 2-3 each

    // ---------------- GEMM1 prologue: chunk 0 ----------------
    #pragma unroll
    for (int j = 0; j < 4; ++j) {
        int idx = tid + j * THREADS;
        int r = idx >> 3, q = (idx & 7) << 2;
        xr[j] = *reinterpret_cast<const float4*>(feaB + r * 256 + q);
    }
    #pragma unroll
    for (int j = 0; j < 3; ++j) {
        int idx = tid + j * THREADS;
        if (idx < 1024) {
            int kr = idx >> 5, q = (idx & 31) << 2;
            wr[j] = *reinterpret_cast<const float4*>(W1 + kr * 128 + q);
        }
    }
    #pragma unroll
    for (int j = 0; j < 4; ++j) {
        int idx = tid + j * THREADS;
        int r = idx >> 3, q = (idx & 7) << 2;
        float4 v = xr[j];
        *reinterpret_cast<float4*>(Xs + r * XS_STRIDE + q) =
            make_float4(to_tf32(v.x), to_tf32(v.y), to_tf32(v.z), to_tf32(v.w));
    }
    #pragma unroll
    for (int j = 0; j < 3; ++j) {
        int idx = tid + j * THREADS;
        if (idx < 1024) {
            int kr = idx >> 5, q = (idx & 31) << 2;
            float4 v = wr[j];
            *reinterpret_cast<float4*>(Ws + kr * WS_STRIDE + q) =
                make_float4(to_tf32(v.x), to_tf32(v.y), to_tf32(v.z), to_tf32(v.w));
        }
    }
    __syncthreads();

    // ---------------- GEMM1 main loop: Y = X * W1 ----------------
    float acc[2][8][4];
    #pragma unroll
    for (int mt = 0; mt < 2; ++mt)
        #pragma unroll
        for (int nt = 0; nt < 8; ++nt)
            #pragma unroll
            for (int i = 0; i < 4; ++i) acc[mt][nt][i] = 0.f;

    #pragma unroll 1
    for (int c = 0; c < 8; ++c) {
        // prefetch next chunk into registers (overlaps with mma below)
        if (c < 7) {
            int k0 = (c + 1) * 32;
            #pragma unroll
            for (int j = 0; j < 4; ++j) {
                int idx = tid + j * THREADS;
                int r = idx >> 3, q = (idx & 7) << 2;
                xr[j] = *reinterpret_cast<const float4*>(feaB + r * 256 + k0 + q);
            }
            #pragma unroll
            for (int j = 0; j < 3; ++j) {
                int idx = tid + j * THREADS;
                if (idx < 1024) {
                    int kr = idx >> 5, q = (idx & 31) << 2;
                    wr[j] = *reinterpret_cast<const float4*>(W1 + (k0 + kr) * 128 + q);
                }
            }
        }

        const float* xb = Xs + (c & 1) * XBUF;
        const float* wb = Ws + (c & 1) * WBUF;
        #pragma unroll
        for (int ks = 0; ks < 4; ++ks) {
            float a[2][4];
            #pragma unroll
            for (int mt = 0; mt < 2; ++mt) {
                const float* ap = xb + (wm * 32 + mt * 16 + g) * XS_STRIDE + ks * 8 + t;
                a[mt][0] = ap[0];
                a[mt][1] = ap[8 * XS_STRIDE];
                a[mt][2] = ap[4];
                a[mt][3] = ap[8 * XS_STRIDE + 4];
            }
            #pragma unroll
            for (int nt = 0; nt < 8; ++nt) {
                const float* bp = wb + (ks * 8 + t) * WS_STRIDE + wn * 64 + nt * 8 + g;
                float b0  = bp[0];
                float b1v = bp[4 * WS_STRIDE];
                mma8(acc[0][nt], a[0][0], a[0][1], a[0][2], a[0][3], b0, b1v);
                mma8(acc[1][nt], a[1][0], a[1][1], a[1][2], a[1][3], b0, b1v);
            }
        }

        // store prefetched chunk into the other buffer.
        // Safe: that buffer was last READ in chunk c-1, and the sync that
        // ended iteration c-1 ordered all those reads before these writes.
        if (c < 7) {
            float* xw = Xs + ((c + 1) & 1) * XBUF;
            float* ww = Ws + ((c + 1) & 1) * WBUF;
            #pragma unroll
            for (int j = 0; j < 4; ++j) {
                int idx = tid + j * THREADS;
                int r = idx >> 3, q = (idx & 7) << 2;
                float4 v = xr[j];
                *reinterpret_cast<float4*>(xw + r * XS_STRIDE + q) =
                    make_float4(to_tf32(v.x), to_tf32(v.y), to_tf32(v.z), to_tf32(v.w));
            }
            #pragma unroll
            for (int j = 0; j < 3; ++j) {
                int idx = tid + j * THREADS;
                if (idx < 1024) {
                    int kr = idx >> 5, q = (idx & 31) << 2;
                    float4 v = wr[j];
                    *reinterpret_cast<float4*>(ww + kr * WS_STRIDE + q) =
                        make_float4(to_tf32(v.x), to_tf32(v.y), to_tf32(v.z), to_tf32(v.w));
                }
            }
        }
        __syncthreads();
    }

    // ---------------- write Y (pre-aggregation, f32) -> Hs ----------------
    // Hs aliases the X/W buffers; the loop ended with __syncthreads().
    #pragma unroll
    for (int mt = 0; mt < 2; ++mt) {
        int r0 = wm * 32 + mt * 16 + g;
        #pragma unroll
        for (int nt = 0; nt < 8; ++nt) {
            int col = wn * 64 + nt * 8 + 2 * t;
            *reinterpret_cast<float2*>(Hs + r0 * HS_STRIDE + col) =
                make_float2(acc[mt][nt][0], acc[mt][nt][1]);
            *reinterpret_cast<float2*>(Hs + (r0 + 8) * HS_STRIDE + col) =
                make_float2(acc[mt][nt][2], acc[mt][nt][3]);
        }
    }
    __syncthreads();

    // ---------------- A_hat pass 1 (+b1, relu, cvt tf32), in place ----------------
    for (int task = tid; task < BPB * 128; task += THREADS) {
        int batch = task >> 7;
        int col   = task & 127;
        float* base = Hs + batch * 14 * HS_STRIDE + col;
        float y[14], h[14];
        #pragma unroll
        for (int i = 0; i < 14; ++i) y[i] = base[i * HS_STRIDE];
        ahat14(y, h);
        float bv = b1[col];
        #pragma unroll
        for (int i = 0; i < 14; ++i) {
            float v = fmaxf(h[i] + bv, 0.f);
            base[i * HS_STRIDE] = to_tf32(v);
        }
    }
    __syncthreads();

    // ---------------- GEMM2: Z = H * W2 ----------------
    float acc2[2][4][4];
    #pragma unroll
    for (int mt = 0; mt < 2; ++mt)
        #pragma unroll
        for (int nt = 0; nt < 4; ++nt)
            #pragma unroll
            for (int i = 0; i < 4; ++i) acc2[mt][nt][i] = 0.f;

    #pragma unroll
    for (int ks = 0; ks < 16; ++ks) {
        float a[2][4];
        #pragma unroll
        for (int mt = 0; mt < 2; ++mt) {
            const float* ap = Hs + (wm * 32 + mt * 16 + g) * HS_STRIDE + ks * 8 + t;
            a[mt][0] = ap[0];
            a[mt][1] = ap[8 * HS_STRIDE];
            a[mt][2] = ap[4];
            a[mt][3] = ap[8 * HS_STRIDE + 4];
        }
        #pragma unroll
        for (int nt = 0; nt < 4; ++nt) {
            const float* bp = W2s + (ks * 8 + t) * W2S_STRIDE + wn * 32 + nt * 8 + g;
            float b0  = bp[0];
            float b1v = bp[4 * W2S_STRIDE];
            mma8(acc2[0][nt], a[0][0], a[0][1], a[0][2], a[0][3], b0, b1v);
            mma8(acc2[1][nt], a[1][0], a[1][1], a[1][2], a[1][3], b0, b1v);
        }
    }
    __syncthreads();   // all Hs reads complete before Zs writes (alias)

    // ---------------- write Z -> Zs ----------------
    #pragma unroll
    for (int mt = 0; mt < 2; ++mt) {
        int r0 = wm * 32 + mt * 16 + g;
        #pragma unroll
        for (int nt = 0; nt < 4; ++nt) {
            int col = wn * 32 + nt * 8 + 2 * t;
            *reinterpret_cast<float2*>(Zs + r0 * ZS_STRIDE + col) =
                make_float2(acc2[mt][nt][0], acc2[mt][nt][1]);
            *reinterpret_cast<float2*>(Zs + (r0 + 8) * ZS_STRIDE + col) =
                make_float2(acc2[mt][nt][2], acc2[mt][nt][3]);
        }
    }
    __syncthreads();

    // ---------------- A_hat pass 2 (+b2) -> global ----------------
    float* gout = out + (size_t)blk * ROWS * 64;
    for (int task = tid; task < BPB * 64; task += THREADS) {
        int batch = task >> 6;
        int col   = task & 63;
        const float* base = Zs + batch * 14 * ZS_STRIDE + col;
        float z[14], o[14];
        #pragma unroll
        for (int i = 0; i < 14; ++i) z[i] = base[i * ZS_STRIDE];
        ahat14(z, o);
        float bv = b2[col];
        #pragma unroll
        for (int m = 0; m < 14; ++m)
            gout[(batch * 14 + m) * 64 + col] = o[m] + bv;
    }
}

extern "C" void kernel_launch(void* const* d_in, const int* in_sizes, int n_in,
                              void* d_out, int out_size) {
    const float* fea = (const float*)d_in[0];
    const float* W1  = (const float*)d_in[1];
    const float* b1  = (const float*)d_in[2];
    const float* W2  = (const float*)d_in[3];
    const float* b2  = (const float*)d_in[4];
    float* out = (float*)d_out;

    int B = in_sizes[0] / (14 * 256);   // 16384
    int blocks = B / BPB;               // 1024

    cudaFuncSetAttribute(gcn_fused_kernel,
                         cudaFuncAttributeMaxDynamicSharedMemorySize, SMEM_BYTES);
    gcn_fused_kernel<<<blocks, THREADS, SMEM_BYTES>>>(fea, W1, b1, W2, b2, out);
}